// round 2
// baseline (speedup 1.0000x reference)
#include <cuda_runtime.h>
#include <cuda_bf16.h>
#include <cstdint>

// LongformerAttention_44315472560501
// output            = hidden_states  (identity copy, 32 MiB f32)
// attention_weights = zeros          (128 MiB f32)
// Block-role-specialized streaming kernel: copy blocks (unroll-4 LDG.128/STG.128,
// MLP=4) and zero blocks (pure STG.128 stream). One-wave grid.

__global__ void copy_zero_split(const float4* __restrict__ src,
                                float4* __restrict__ dst,
                                long long n_copy4,
                                long long n_total4,
                                int copy_blocks)
{
    const int tx = threadIdx.x;
    const int bd = blockDim.x;

    if (blockIdx.x < (unsigned)copy_blocks) {
        // ---- pure copy over [0, n_copy4) ----
        const long long chunk  = 4LL * bd;                 // float4s per block-iter
        const long long stride = (long long)copy_blocks * chunk;
        long long base = (long long)blockIdx.x * chunk;

        for (; base + chunk <= n_copy4; base += stride) {
            // 4 independent loads first (MLP=4), then 4 stores
            float4 a = src[base + tx];
            float4 b = src[base + tx + bd];
            float4 c = src[base + tx + 2 * bd];
            float4 d = src[base + tx + 3 * bd];
            dst[base + tx]          = a;
            dst[base + tx + bd]     = b;
            dst[base + tx + 2 * bd] = c;
            dst[base + tx + 3 * bd] = d;
        }
        // remainder (copy region not a multiple of chunk*copy_blocks)
        for (long long i = base + tx; i < n_copy4; i += (long long)copy_blocks * bd) {
            dst[i] = src[i];
        }
    } else {
        // ---- pure zero-fill over [n_copy4, n_total4) ----
        const int zb  = blockIdx.x - copy_blocks;
        const int nzb = gridDim.x - copy_blocks;
        float4* __restrict__ zdst = dst + n_copy4;
        const long long n_zero4 = n_total4 - n_copy4;
        const float4 z = make_float4(0.f, 0.f, 0.f, 0.f);

        const long long chunk  = 4LL * bd;
        const long long stride = (long long)nzb * chunk;
        long long base = (long long)zb * chunk;

        for (; base + chunk <= n_zero4; base += stride) {
            zdst[base + tx]          = z;
            zdst[base + tx + bd]     = z;
            zdst[base + tx + 2 * bd] = z;
            zdst[base + tx + 3 * bd] = z;
        }
        for (long long i = base + tx; i < n_zero4; i += (long long)nzb * bd) {
            zdst[i] = z;
        }
    }
}

__global__ void tail_scalar(const float* __restrict__ src,
                            float* __restrict__ dst,
                            long long start,
                            long long n_copy,
                            long long n_total)
{
    long long i = start + blockIdx.x * blockDim.x + threadIdx.x;
    if (i < n_total) {
        dst[i] = (i < n_copy) ? src[i] : 0.f;
    }
}

extern "C" void kernel_launch(void* const* d_in, const int* in_sizes, int n_in,
                              void* d_out, int out_size)
{
    const float* hidden = (const float*)d_in[0];
    float* out = (float*)d_out;

    long long n_total = (long long)out_size;
    long long n_copy  = (long long)in_sizes[0];
    if (n_copy > n_total) n_copy = n_total;

    long long n_total4 = n_total / 4;
    long long n_copy4  = n_copy  / 4;
    long long n_zero4  = n_total4 - n_copy4;

    if (n_total4 > 0) {
        const int threads = 256;
        int blocks = 148 * 8;  // one wave at 2048 thr/SM

        // apportion blocks by traffic: copy counts 2x (read + write)
        long long copy_traffic = 2 * n_copy4;
        long long zero_traffic = n_zero4;
        long long tot_traffic  = copy_traffic + zero_traffic;
        int copy_blocks;
        if (tot_traffic <= 0) {
            copy_blocks = n_copy4 > 0 ? blocks : 0;
        } else {
            copy_blocks = (int)((copy_traffic * blocks + tot_traffic - 1) / tot_traffic);
        }
        if (n_copy4 > 0 && copy_blocks < 1) copy_blocks = 1;
        if (n_zero4 > 0 && copy_blocks > blocks - 1) copy_blocks = blocks - 1;
        if (n_copy4 == 0) copy_blocks = 0;

        copy_zero_split<<<blocks, threads>>>(
            (const float4*)hidden, (float4*)out, n_copy4, n_total4, copy_blocks);
    }

    long long done = n_total4 * 4;
    if (done < n_total) {
        long long rem = n_total - done;
        int threads = 128;
        int blocks = (int)((rem + threads - 1) / threads);
        tail_scalar<<<blocks, threads>>>(hidden, out, done, n_copy, n_total);
    }
}

// round 3
// speedup vs baseline: 1.1762x; 1.1762x over previous
#include <cuda_runtime.h>
#include <cuda_bf16.h>
#include <cstdint>

// LongformerAttention_44315472560501
// output            = hidden_states  (identity copy, 32 MiB f32)
// attention_weights = zeros          (128 MiB f32)
//
// R3: delegate to the driver's tuned streaming paths as CUDA-graph nodes.
//   - cudaMemcpyAsync D2D for the identity copy (becomes a memcpy node)
//   - cudaMemsetAsync for the zero region     (becomes a memset node)
// Both are graph-capturable and allocation-free. Two hand-written kernels
// (R1 grid-stride predicated, R2 role-split MLP-4) both plateaued at
// ~4.2 TB/s effective; this tests whether the driver paths clear that.
//
// Fallback tail kernel handles any non-16B-aligned remainder (not expected
// for this shape, but keeps the kernel shape-agnostic and correct).

__global__ void tail_scalar(const float* __restrict__ src,
                            float* __restrict__ dst,
                            long long start,
                            long long n_copy,
                            long long n_total)
{
    long long i = start + (long long)blockIdx.x * blockDim.x + threadIdx.x;
    if (i < n_total) {
        dst[i] = (i < n_copy) ? src[i] : 0.f;
    }
}

extern "C" void kernel_launch(void* const* d_in, const int* in_sizes, int n_in,
                              void* d_out, int out_size)
{
    const float* hidden = (const float*)d_in[0];
    float* out = (float*)d_out;

    long long n_total = (long long)out_size;
    long long n_copy  = (long long)in_sizes[0];
    if (n_copy > n_total) n_copy = n_total;
    long long n_zero = n_total - n_copy;

    if (n_copy > 0) {
        cudaMemcpyAsync(out, hidden, (size_t)n_copy * sizeof(float),
                        cudaMemcpyDeviceToDevice, 0);
    }
    if (n_zero > 0) {
        cudaMemsetAsync(out + n_copy, 0, (size_t)n_zero * sizeof(float), 0);
    }
}